// round 8
// baseline (speedup 1.0000x reference)
#include <cuda_runtime.h>
#include <cstdint>
#include <cstddef>

#define BB 2
#define TT 2048
#define DD 1024
#define HH 16
#define HS 64
#define BT (BB*TT)

// Scratch (allocation-free rule: __device__ globals)
__device__ float g_q[BB*HH*TT*HS];
__device__ float g_k[BB*HH*TT*HS];
__device__ float g_v[BB*HH*TT*HS];
__device__ float g_y[BT*DD];

__device__ __forceinline__ uint32_t f2tf(float x){
    uint32_t r; asm("cvt.rna.tf32.f32 %0, %1;" : "=r"(r) : "f"(x)); return r;
}
__device__ __forceinline__ float f2tff(float x){ return __uint_as_float(f2tf(x)); }

__device__ __forceinline__ void mma8(float* c, const uint32_t* a, const uint32_t* b){
    asm volatile(
        "mma.sync.aligned.m16n8k8.row.col.f32.tf32.tf32.f32 "
        "{%0,%1,%2,%3}, {%4,%5,%6,%7}, {%8,%9}, {%0,%1,%2,%3};\n"
        : "+f"(c[0]), "+f"(c[1]), "+f"(c[2]), "+f"(c[3])
        : "r"(a[0]), "r"(a[1]), "r"(a[2]), "r"(a[3]), "r"(b[0]), "r"(b[1]));
}

__device__ __forceinline__ void cpa16(float* dst_smem, const float* src){
    uint32_t d = (uint32_t)__cvta_generic_to_shared(dst_smem);
    asm volatile("cp.async.cg.shared.global [%0], [%1], 16;\n" :: "r"(d), "l"(src));
}
#define CPA_COMMIT() asm volatile("cp.async.commit_group;\n" ::: "memory")
#define CPA_WAIT0()  asm volatile("cp.async.wait_group 0;\n" ::: "memory")
#define CPA_WAIT1()  asm volatile("cp.async.wait_group 1;\n" ::: "memory")

// ---------------------------------------------------------------------------
// 128x128 tile of A(MxK row-major) * W^T (W is NxK row-major), K = DD = 1024.
// cp.async double-buffered, k-chunk 32, one barrier per chunk.
// 256 threads, 8 warps; warp tile 64x32. tf32 conversion at fragment load.
// ---------------------------------------------------------------------------
__device__ __forceinline__ void gemm_128_128(
    const float* __restrict__ A, const float* __restrict__ W,
    int m0, int n0, float acc[16][4], float* sm)
{
    float* sAb[2] = { sm,          sm + 4608 };
    float* sBb[2] = { sm + 9216,   sm + 13824 };

    const int t = threadIdx.x, lane = t & 31, warp = t >> 5;
    const int wm = (warp >> 2) * 64, wn = (warp & 3) * 32;
    const int r = lane >> 2, c = lane & 3;
    const int lrow = t >> 3, lc4 = (t & 7) * 4;

    #pragma unroll
    for (int i = 0; i < 16; i++){ acc[i][0]=acc[i][1]=acc[i][2]=acc[i][3]=0.f; }

    // prefetch chunk 0
    #pragma unroll
    for (int i = 0; i < 4; i++){
        cpa16(sAb[0] + (lrow + 32*i)*36 + lc4, A + (size_t)(m0 + lrow + 32*i)*DD + lc4);
        cpa16(sBb[0] + (lrow + 32*i)*36 + lc4, W + (size_t)(n0 + lrow + 32*i)*DD + lc4);
    }
    CPA_COMMIT();

    for (int ch = 0; ch < 32; ch++){
        CPA_WAIT0();
        __syncthreads();
        if (ch < 31){
            const int k0 = (ch + 1) * 32;
            float* dA = sAb[(ch + 1) & 1];
            float* dB = sBb[(ch + 1) & 1];
            #pragma unroll
            for (int i = 0; i < 4; i++){
                cpa16(dA + (lrow + 32*i)*36 + lc4, A + (size_t)(m0 + lrow + 32*i)*DD + k0 + lc4);
                cpa16(dB + (lrow + 32*i)*36 + lc4, W + (size_t)(n0 + lrow + 32*i)*DD + k0 + lc4);
            }
            CPA_COMMIT();
        }
        const float* sA = sAb[ch & 1];
        const float* sB = sBb[ch & 1];
        #pragma unroll
        for (int ks = 0; ks < 4; ks++){
            uint32_t af[4][4], bf[4][2];
            #pragma unroll
            for (int mt = 0; mt < 4; mt++){
                const float* p = sA + (wm + mt*16 + r)*36 + ks*8 + c;
                af[mt][0] = f2tf(p[0]);
                af[mt][1] = f2tf(p[8*36]);
                af[mt][2] = f2tf(p[4]);
                af[mt][3] = f2tf(p[8*36 + 4]);
            }
            #pragma unroll
            for (int nt = 0; nt < 4; nt++){
                const float* p = sB + (wn + nt*8 + r)*36 + ks*8 + c;
                bf[nt][0] = f2tf(p[0]);
                bf[nt][1] = f2tf(p[4]);
            }
            #pragma unroll
            for (int mt = 0; mt < 4; mt++)
                #pragma unroll
                for (int nt = 0; nt < 4; nt++)
                    mma8(acc[mt*4 + nt], af[mt], bf[nt]);
        }
    }
}

// ---------------------------------------------------------------------------
// K1: QKV projection.  grid (32, 8, 3), 256 thr, 2 CTAs/SM.
// ---------------------------------------------------------------------------
extern "C" __global__ void __launch_bounds__(256, 2)
qkv_kernel(const float* __restrict__ x, const float* __restrict__ Wq,
           const float* __restrict__ Wk, const float* __restrict__ Wv)
{
    extern __shared__ float smg[];
    const float* W = (blockIdx.z == 0) ? Wq : ((blockIdx.z == 1) ? Wk : Wv);
    float* dst     = (blockIdx.z == 0) ? g_q : ((blockIdx.z == 1) ? g_k : g_v);
    const int m0 = blockIdx.x * 128, n0 = blockIdx.y * 128;

    float acc[16][4];
    gemm_128_128(x, W, m0, n0, acc, smg);

    const int lane = threadIdx.x & 31, warp = threadIdx.x >> 5;
    const int wm = (warp >> 2) * 64, wn = (warp & 3) * 32;
    const int r = lane >> 2, c = lane & 3;
    #pragma unroll
    for (int mt = 0; mt < 4; mt++){
        #pragma unroll
        for (int nt = 0; nt < 4; nt++){
            const float* f = acc[mt*4 + nt];
            const int m_ = m0 + wm + mt*16 + r;
            const int n_ = n0 + wn + nt*8 + c*2;
            const int b  = m_ >> 11, h = n_ >> 6, hs = n_ & 63;
            const int t0 = m_ & 2047, t1 = (m_ + 8) & 2047;
            float2 v0 = make_float2(f2tff(f[0]), f2tff(f[1]));
            float2 v1 = make_float2(f2tff(f[2]), f2tff(f[3]));
            *(float2*)(dst + ((size_t)((b<<4) + h)*TT + t0)*HS + hs) = v0;
            *(float2*)(dst + ((size_t)((b<<4) + h)*TT + t1)*HS + hs) = v1;
        }
    }
}

// ---------------------------------------------------------------------------
// K2: fused attention.  grid (16, 16, 2), 256 thr.
// cp.async double-buffered K, early-prefetched V; one/two bars per K-tile.
// ---------------------------------------------------------------------------
#define SQ_OFF 0
#define SK0_OFF 8704
#define SK1_OFF 17408
#define SV_OFF 26112
#define SP_OFF 35328
#define SL_OFF 52224
// total 52352 floats = 209408 B

extern "C" __global__ void __launch_bounds__(256, 1)
attn_kernel(float* __restrict__ att)
{
    extern __shared__ float sm[];
    float* sQ = sm + SQ_OFF;           // 128 x 68
    float* sKb[2] = { sm + SK0_OFF, sm + SK1_OFF };  // 128 x 68 each
    float* sV = sm + SV_OFF;           // 128 x 72
    float* sP = sm + SP_OFF;           // 128 x 132
    float* sL = sm + SL_OFF;           // 128

    const int t = threadIdx.x, lane = t & 31, warp = t >> 5;
    const int r = lane >> 2, c = lane & 3;
    const int qb = blockIdx.x, h = blockIdx.y, b = blockIdx.z;

    const size_t headoff = (size_t)(b*HH + h) * TT * HS;
    const float* Qg = g_q + headoff + (size_t)qb * 128 * HS;
    const float* Kg = g_k + headoff;
    const float* Vg = g_v + headoff;
    float* attg = att + ((size_t)(b*HH + h)*TT + (size_t)qb*128) * TT;

    // load Q tile (async) then K[0]
    #pragma unroll
    for (int i = 0; i < 8; i++){
        const int idx = t + 256*i, row = idx >> 4, col = (idx & 15) * 4;
        cpa16(sQ + row*68 + col, Qg + row*64 + col);
    }
    CPA_COMMIT();
    #pragma unroll
    for (int i = 0; i < 8; i++){
        const int idx = t + 256*i, row = idx >> 4, col = (idx & 15) * 4;
        cpa16(sKb[0] + row*68 + col, Kg + (size_t)row*64 + col);
    }
    CPA_COMMIT();
    CPA_WAIT1();            // Q ready, K[0] still in flight
    __syncthreads();

    // preload Q A-fragments (fixed for whole CTA lifetime)
    uint32_t aq[8][4];
    #pragma unroll
    for (int ks = 0; ks < 8; ks++){
        const float* p = sQ + (warp*16 + r)*68 + ks*8 + c;
        aq[ks][0] = __float_as_uint(p[0]);
        aq[ks][1] = __float_as_uint(p[8*68]);
        aq[ks][2] = __float_as_uint(p[4]);
        aq[ks][3] = __float_as_uint(p[8*68 + 4]);
    }

    const float CF = 0.18033688011112042f;   // log2(e) / sqrt(64)

    // ---- PASS 1: row sums of exp(s) ----
    float l0 = 0.f, l1 = 0.f;
    for (int kb = 0; kb < 16; kb++){
        CPA_WAIT0();
        __syncthreads();
        if (kb < 15){
            float* dK = sKb[(kb + 1) & 1];
            #pragma unroll
            for (int i = 0; i < 8; i++){
                const int idx = t + 256*i, row = idx >> 4, col = (idx & 15) * 4;
                cpa16(dK + row*68 + col, Kg + (size_t)((kb+1)*128 + row)*64 + col);
            }
            CPA_COMMIT();
        }
        const float* sK = sKb[kb & 1];

        float s[16][4];
        #pragma unroll
        for (int i = 0; i < 16; i++){ s[i][0]=s[i][1]=s[i][2]=s[i][3]=0.f; }
        #pragma unroll
        for (int ks = 0; ks < 8; ks++){
            #pragma unroll
            for (int nt = 0; nt < 16; nt++){
                uint32_t bf[2];
                const float* p = sK + (nt*8 + r)*68 + ks*8 + c;
                bf[0] = __float_as_uint(p[0]);
                bf[1] = __float_as_uint(p[4]);
                mma8(s[nt], aq[ks], bf);
            }
        }
        #pragma unroll
        for (int nt = 0; nt < 16; nt++){
            l0 += exp2f(s[nt][0]*CF) + exp2f(s[nt][1]*CF);
            l1 += exp2f(s[nt][2]*CF) + exp2f(s[nt][3]*CF);
        }
    }
    l0 += __shfl_xor_sync(0xffffffffu, l0, 1);
    l0 += __shfl_xor_sync(0xffffffffu, l0, 2);
    l1 += __shfl_xor_sync(0xffffffffu, l1, 1);
    l1 += __shfl_xor_sync(0xffffffffu, l1, 2);
    __syncthreads();
    if (c == 0){ sL[warp*16 + r] = l0; sL[warp*16 + r + 8] = l1; }
    __syncthreads();
    const float inv0 = 1.0f / sL[warp*16 + r];
    const float inv1 = 1.0f / sL[warp*16 + r + 8];

    // ---- PASS 2: att store + P*V ----
    float yv[8][4];
    #pragma unroll
    for (int i = 0; i < 8; i++){ yv[i][0]=yv[i][1]=yv[i][2]=yv[i][3]=0.f; }

    // prefetch K[0] again
    #pragma unroll
    for (int i = 0; i < 8; i++){
        const int idx = t + 256*i, row = idx >> 4, col = (idx & 15) * 4;
        cpa16(sKb[0] + row*68 + col, Kg + (size_t)row*64 + col);
    }
    CPA_COMMIT();

    for (int kb = 0; kb < 16; kb++){
        CPA_WAIT0();
        __syncthreads();          // K[kb] ready; all warps done with prev iter (sP, sV free)

        // V[kb] (group committed FIRST so wait_group 1 retires it, keeps K[kb+1])
        #pragma unroll
        for (int i = 0; i < 8; i++){
            const int idx = t + 256*i, row = idx >> 4, col = (idx & 15) * 4;
            cpa16(sV + row*72 + col, Vg + (size_t)(kb*128 + row)*64 + col);
        }
        CPA_COMMIT();
        if (kb < 15){
            float* dK = sKb[(kb + 1) & 1];
            #pragma unroll
            for (int i = 0; i < 8; i++){
                const int idx = t + 256*i, row = idx >> 4, col = (idx & 15) * 4;
                cpa16(dK + row*68 + col, Kg + (size_t)((kb+1)*128 + row)*64 + col);
            }
            CPA_COMMIT();
        }
        const float* sK = sKb[kb & 1];

        float s[16][4];
        #pragma unroll
        for (int i = 0; i < 16; i++){ s[i][0]=s[i][1]=s[i][2]=s[i][3]=0.f; }
        #pragma unroll
        for (int ks = 0; ks < 8; ks++){
            #pragma unroll
            for (int nt = 0; nt < 16; nt++){
                uint32_t bf[2];
                const float* p = sK + (nt*8 + r)*68 + ks*8 + c;
                bf[0] = __float_as_uint(p[0]);
                bf[1] = __float_as_uint(p[4]);
                mma8(s[nt], aq[ks], bf);
            }
        }
        // normalized probabilities -> smem P tile (STS.64)
        #pragma unroll
        for (int nt = 0; nt < 16; nt++){
            float p0 = exp2f(s[nt][0]*CF) * inv0;
            float p1 = exp2f(s[nt][1]*CF) * inv0;
            float p2 = exp2f(s[nt][2]*CF) * inv1;
            float p3 = exp2f(s[nt][3]*CF) * inv1;
            float* pp = sP + (warp*16 + r)*132 + nt*8 + 2*c;
            *(float2*)(pp)         = make_float2(p0, p1);
            *(float2*)(pp + 8*132) = make_float2(p2, p3);
        }
        if (kb < 15) { CPA_WAIT1(); } else { CPA_WAIT0(); }  // V ready (K[kb+1] stays in flight)
        __syncthreads();

        // coalesced att store (float4 rows from sP)
        #pragma unroll
        for (int i = 0; i < 16; i++){
            const int idx = t + 256*i, row = idx >> 5, c4 = (idx & 31) * 4;
            *(float4*)(attg + (size_t)row*TT + kb*128 + c4) = *(const float4*)(sP + row*132 + c4);
        }
        // Y += P * V
        #pragma unroll
        for (int ks = 0; ks < 16; ks++){
            uint32_t ap[4];
            const float* p = sP + (warp*16 + r)*132 + ks*8 + c;
            ap[0] = __float_as_uint(p[0]);
            ap[1] = __float_as_uint(p[8*132]);
            ap[2] = __float_as_uint(p[4]);
            ap[3] = __float_as_uint(p[8*132 + 4]);
            #pragma unroll
            for (int nt = 0; nt < 8; nt++){
                uint32_t bv[2];
                const float* q2 = sV + (ks*8 + c)*72 + nt*8 + r;
                bv[0] = __float_as_uint(q2[0]);
                bv[1] = __float_as_uint(q2[4*72]);
                mma8(yv[nt], ap, bv);
            }
        }
    }

    // write Y to g_y in [B,T,D] layout
    #pragma unroll
    for (int nt = 0; nt < 8; nt++){
        const int row = qb*128 + warp*16 + r;
        const int col = h*64 + nt*8 + 2*c;
        *(float2*)(g_y + ((size_t)b*TT + row)*DD + col)     = make_float2(yv[nt][0], yv[nt][1]);
        *(float2*)(g_y + ((size_t)b*TT + row + 8)*DD + col) = make_float2(yv[nt][2], yv[nt][3]);
    }
}

// ---------------------------------------------------------------------------
// K3: output projection + bias.  grid (32, 8), 256 thr, 2 CTAs/SM.
// ---------------------------------------------------------------------------
extern "C" __global__ void __launch_bounds__(256, 2)
oproj_kernel(const float* __restrict__ Wo, const float* __restrict__ bo,
             float* __restrict__ out)
{
    extern __shared__ float smg[];
    const int m0 = blockIdx.x * 128, n0 = blockIdx.y * 128;

    float acc[16][4];
    gemm_128_128(g_y, Wo, m0, n0, acc, smg);

    const int lane = threadIdx.x & 31, warp = threadIdx.x >> 5;
    const int wm = (warp >> 2) * 64, wn = (warp & 3) * 32;
    const int r = lane >> 2, c = lane & 3;
    #pragma unroll
    for (int mt = 0; mt < 4; mt++){
        #pragma unroll
        for (int nt = 0; nt < 4; nt++){
            const float* f = acc[mt*4 + nt];
            const int m_ = m0 + wm + mt*16 + r;
            const int n_ = n0 + wn + nt*8 + c*2;
            const float2 bias = *(const float2*)(bo + n_);
            float2 v0 = make_float2(f[0] + bias.x, f[1] + bias.y);
            float2 v1 = make_float2(f[2] + bias.x, f[3] + bias.y);
            *(float2*)(out + (size_t)m_*DD + n_)       = v0;
            *(float2*)(out + (size_t)(m_ + 8)*DD + n_) = v1;
        }
    }
}

// ---------------------------------------------------------------------------
extern "C" void kernel_launch(void* const* d_in, const int* in_sizes, int n_in,
                              void* d_out, int out_size)
{
    (void)in_sizes; (void)n_in; (void)out_size;
    const float* x  = (const float*)d_in[0];
    const float* Wq = (const float*)d_in[1];
    const float* Wk = (const float*)d_in[2];
    const float* Wv = (const float*)d_in[3];
    const float* Wo = (const float*)d_in[4];
    const float* bo = (const float*)d_in[5];

    float* y_out = (float*)d_out;                       // [B,T,D]
    float* att   = y_out + (size_t)BT * DD;             // [B,H,T,T]

    const int gemm_smem = 18432 * 4;    // 73728 B (double-buffered A+B)
    const int attn_smem = 52352 * 4;    // 209408 B
    cudaFuncSetAttribute(qkv_kernel,  cudaFuncAttributeMaxDynamicSharedMemorySize, gemm_smem);
    cudaFuncSetAttribute(oproj_kernel,cudaFuncAttributeMaxDynamicSharedMemorySize, gemm_smem);
    cudaFuncSetAttribute(attn_kernel, cudaFuncAttributeMaxDynamicSharedMemorySize, attn_smem);

    qkv_kernel<<<dim3(32, 8, 3), 256, gemm_smem>>>(x, Wq, Wk, Wv);
    attn_kernel<<<dim3(16, 16, 2), 256, attn_smem>>>(att);
    oproj_kernel<<<dim3(32, 8), 256, gemm_smem>>>(Wo, bo, y_out);
}